// round 7
// baseline (speedup 1.0000x reference)
#include <cuda_runtime.h>
#include <cuda_bf16.h>
#include <math_constants.h>
#include <cstdint>

#define BB 8
#define EE 100
#define FPAD 4096
#define NTILE 64          // n rows per CTA tile
#define FCH 128           // f cols per chunk
#define FSPLIT 2
#define KROW 128          // bf16 per stored row (256B), zeros past 99
#define NKS 7             // 7 x k16 = 112 (zeros past 99 contribute 0)

// smem layout
#define ENT_HALF (NTILE*128)            // 8192
#define FACT_HALF (FCH*128)             // 16384
#define SM_ENT 0                        // 2 halves = 16KB
#define SM_FACT (2*ENT_HALF)            // 2 buffers x 2 halves = 64KB
#define FACT_BUF (2*FACT_HALF)
#define SM_A (SM_FACT + 2*FACT_BUF)     // 2 buffers of [128 f][8 b] bf16
#define A_BUF 2048
#define SM_TOTAL (SM_A + 2*A_BUF)       // 86016 B  (x2 CTAs = 168KB/SM)

// ---- device scratch ----
__device__ __nv_bfloat16 g_Ab[2][FPAD][BB];    // A transposed (bf16), +INF for f>=F
__device__ float g_e2[FPAD];
__device__ float g_min[2][BB][FPAD];
__device__ __nv_bfloat16 g_eb[FPAD * KROW];    // -2*ent
__device__ __nv_bfloat16 g_fb[2][FPAD * KROW]; // [0]=fa2(sp), [1]=fa1(po)
__device__ int g_cnt[2][FPAD / NTILE];         // arrival counters per (z, n-tile)

// ---- helpers ----
__device__ __forceinline__ unsigned swz(unsigned b) { return b ^ ((b >> 3) & 0x70); }
__device__ __forceinline__ unsigned smem_u32(const void* p) {
  return (unsigned)__cvta_generic_to_shared(p);
}
__device__ __forceinline__ void cp16(unsigned dst, const void* src) {
  asm volatile("cp.async.cg.shared.global [%0], [%1], 16;" :: "r"(dst), "l"(src));
}
__device__ __forceinline__ void ldmx4(uint32_t* r, unsigned addr) {
  asm volatile("ldmatrix.sync.aligned.m8n8.x4.shared.b16 {%0,%1,%2,%3}, [%4];"
               : "=r"(r[0]), "=r"(r[1]), "=r"(r[2]), "=r"(r[3]) : "r"(addr));
}
__device__ __forceinline__ void mma16816(float* c, const uint32_t* a,
                                         uint32_t b0, uint32_t b1) {
  asm volatile("mma.sync.aligned.m16n8k16.row.col.f32.bf16.bf16.f32 "
               "{%0,%1,%2,%3}, {%4,%5,%6,%7}, {%8,%9}, {%0,%1,%2,%3};"
               : "+f"(c[0]), "+f"(c[1]), "+f"(c[2]), "+f"(c[3])
               : "r"(a[0]), "r"(a[1]), "r"(a[2]), "r"(a[3]), "r"(b0), "r"(b1));
}
__device__ __forceinline__ uint32_t bcvt2(float x) {
  uint32_t r; asm("cvt.rn.bf16x2.f32 %0, %1, %1;" : "=r"(r) : "f"(x)); return r;
}
__device__ __forceinline__ uint32_t addbf2(uint32_t a, uint32_t b) {
  uint32_t r; asm("add.rn.bf16x2 %0, %1, %2;" : "=r"(r) : "r"(a), "r"(b)); return r;
}
__device__ __forceinline__ uint32_t minbf2(uint32_t a, uint32_t b) {
  uint32_t r; asm("min.bf16x2 %0, %1, %2;" : "=r"(r) : "r"(a), "r"(b)); return r;
}
__device__ __forceinline__ void atomicMinF(float* addr, float v) {
  if (v >= 0.0f) atomicMin((int*)addr, __float_as_int(v));
  else           atomicMax((unsigned int*)addr, __float_as_uint(v));
}

// ---- fused prep kernel: blockIdx.y selects task ----
__global__ void k_prep(const float* __restrict__ rel, const float* __restrict__ a1,
                       const float* __restrict__ a2, const float* __restrict__ fr,
                       const float* __restrict__ f1, const float* __restrict__ f2,
                       const float* __restrict__ ent, int N, int F) {
  const int sel = blockIdx.y;
  const int tid = threadIdx.x;

  if (sel == 0) {
    if (blockIdx.x >= (FPAD * BB) / 256) return;
    __shared__ __align__(16) float q[3][BB][EE];
    for (int i = tid; i < 3 * BB * EE; i += 256) {
      int t = i / (BB * EE), rem = i - t * (BB * EE);
      int b = rem / EE, e = rem - b * EE;
      const float* s = (t == 0) ? rel : (t == 1 ? a1 : a2);
      q[t][b][e] = s[b * EE + e];
    }
    __syncthreads();
    int idx = blockIdx.x * 256 + tid;
    int f = idx >> 3, b = idx & 7;
    if (f >= F) {
      g_Ab[0][f][b] = __float2bfloat16(CUDART_INF_F);
      g_Ab[1][f][b] = __float2bfloat16(CUDART_INF_F);
      return;
    }
    const float4* pr = (const float4*)(fr + (size_t)f * EE);
    const float4* p1 = (const float4*)(f1 + (size_t)f * EE);
    const float4* p2 = (const float4*)(f2 + (size_t)f * EE);
    float sr = 0.f, s1v = 0.f, s2v = 0.f, n1 = 0.f, n2 = 0.f;
#pragma unroll 5
    for (int e4 = 0; e4 < EE / 4; e4++) {
      float4 vr = pr[e4], v1 = p1[e4], v2 = p2[e4];
      n1 += v1.x * v1.x + v1.y * v1.y + v1.z * v1.z + v1.w * v1.w;
      n2 += v2.x * v2.x + v2.y * v2.y + v2.z * v2.z + v2.w * v2.w;
      float4 qr = *(const float4*)&q[0][b][e4 * 4];
      float4 q1 = *(const float4*)&q[1][b][e4 * 4];
      float4 q2 = *(const float4*)&q[2][b][e4 * 4];
      float t;
      t = qr.x - vr.x; sr += t * t;  t = qr.y - vr.y; sr += t * t;
      t = qr.z - vr.z; sr += t * t;  t = qr.w - vr.w; sr += t * t;
      t = q1.x - v1.x; s1v += t * t; t = q1.y - v1.y; s1v += t * t;
      t = q1.z - v1.z; s1v += t * t; t = q1.w - v1.w; s1v += t * t;
      t = q2.x - v2.x; s2v += t * t; t = q2.y - v2.y; s2v += t * t;
      t = q2.z - v2.z; s2v += t * t; t = q2.w - v2.w; s2v += t * t;
    }
    g_Ab[0][f][b] = __float2bfloat16(sr + s1v + n2);  // sp pairs with fa2
    g_Ab[1][f][b] = __float2bfloat16(sr + s2v + n1);  // po pairs with fa1
  } else if (sel == 1) {
    if (blockIdx.x >= FPAD / 256) return;
    int n = blockIdx.x * 256 + tid;
    if (n >= N) return;
    const float4* e4p = (const float4*)ent;
    float s = 0.f;
#pragma unroll
    for (int qq = 0; qq < EE / 4; qq++) {
      float4 v = e4p[n * (EE / 4) + qq];
      s += v.x * v.x + v.y * v.y + v.z * v.z + v.w * v.w;
    }
    g_e2[n] = s;
  } else if (sel <= 4) {
    int idx = blockIdx.x * 256 + tid;
    int r = idx >> 7, j = idx & 127;
    const float* src = (sel == 2) ? ent : (sel == 3 ? f2 : f1);
    int rows = (sel == 2) ? N : F;
    float scale = (sel == 2) ? -2.0f : 1.0f;
    float v = (r < rows && j < EE) ? scale * src[r * EE + j] : 0.f;
    __nv_bfloat16* dst = (sel == 2) ? g_eb : g_fb[sel - 3];
    dst[idx] = __float2bfloat16(v);
  } else {
    int i = blockIdx.x * 256 + tid;
    if (i < 2 * BB * FPAD) ((float*)g_min)[i] = CUDART_INF_F;
    if (i < 2 * (FPAD / NTILE)) ((int*)g_cnt)[i] = 0;
  }
}

// ---- main HMMA kernel (finalize fused via arrival counters) ----
__global__ __launch_bounds__(256, 2) void k_main(float* __restrict__ out, int N) {
  extern __shared__ char sm[];
  const int tid = threadIdx.x;
  const int wid = tid >> 5;
  const int lane = tid & 31;
  const unsigned smb = smem_u32(sm);
  const int z = blockIdx.z;
  const int n0 = blockIdx.x * NTILE;
  const int f0base = blockIdx.y * (FPAD / FSPLIT);
  const int NCH = (FPAD / FSPLIT) / FCH;   // 16
  const __nv_bfloat16* fb = g_fb[z];

  const int wn = wid & 1, wf = wid >> 1;   // warp grid 2(n) x 4(f)
  const int g = lane >> 2, tl = lane & 3;
  const int lrow = lane & 7, mm = lane >> 3;

  // ldmatrix per-lane bases
  const int xoff = 16 * (mm >> 1);
  unsigned aRowOff[2], aXor[2];
#pragma unroll
  for (int mi = 0; mi < 2; mi++) {
    int r = 32 * wn + 16 * mi + lrow + 8 * (mm & 1);
    aRowOff[mi] = r * 128;
    aXor[mi] = (r & 7) * 16;
  }
  unsigned bRowOff[2], bXor[2];
#pragma unroll
  for (int njp = 0; njp < 2; njp++) {
    int r = 32 * wf + 16 * njp + lrow + 8 * (mm & 1);
    bRowOff[njp] = r * 128;
    bXor[njp] = (r & 7) * 16;
  }

  // staging helpers (rows x 256B source rows, split into 2 swizzled halves)
  auto stage_ent = [&]() {
    const char* sb = (const char*)(g_eb + (size_t)n0 * KROW);
#pragma unroll
    for (int i = 0; i < 4; i++) {
      int idx = tid + i * 256;              // 0..1023
      int half = idx >> 9;
      int rem = idx & 511;
      int r = rem >> 3, gg = rem & 7;
      cp16(smb + SM_ENT + half * ENT_HALF + swz(r * 128 + gg * 16),
           sb + (size_t)r * 256 + half * 128 + gg * 16);
    }
  };
  auto stage_fact = [&](int c, int bi) {
    const char* sb = (const char*)(fb + (size_t)(f0base + c * FCH) * KROW);
    unsigned dstBase = smb + SM_FACT + bi * FACT_BUF;
#pragma unroll
    for (int i = 0; i < 8; i++) {
      int idx = tid + i * 256;              // 0..2047
      int half = idx >> 10;
      int rem = idx & 1023;
      int r = rem >> 3, gg = rem & 7;
      cp16(dstBase + half * FACT_HALF + swz(r * 128 + gg * 16),
           sb + (size_t)r * 256 + half * 128 + gg * 16);
    }
  };
  auto stage_A = [&](int c, int bi) {
    if (tid < FCH) {
      int f0 = f0base + c * FCH;
      cp16(smb + SM_A + bi * A_BUF + tid * 16, &g_Ab[z][f0 + tid][0]);
    }
  };

  stage_ent();
  stage_fact(0, 0);
  stage_A(0, 0);
  asm volatile("cp.async.commit_group;");

  uint32_t rmP[2][2][4];   // [mi][rowhalf][b-pair], bf16x2, init +INF|+INF
#pragma unroll
  for (int mi = 0; mi < 2; mi++)
#pragma unroll
    for (int h = 0; h < 2; h++)
#pragma unroll
      for (int j = 0; j < 4; j++) rmP[mi][h][j] = 0x7F807F80u;

  for (int c = 0; c < NCH; c++) {
    const int buf = c & 1;
    asm volatile("cp.async.wait_group 0;");
    __syncthreads();
    if (c + 1 < NCH) {
      stage_fact(c + 1, buf ^ 1);
      stage_A(c + 1, buf ^ 1);
      asm volatile("cp.async.commit_group;");
    }

    float acc[2][4][4];
#pragma unroll
    for (int mi = 0; mi < 2; mi++)
#pragma unroll
      for (int nj = 0; nj < 4; nj++)
#pragma unroll
        for (int k = 0; k < 4; k++) acc[mi][nj][k] = 0.f;

    const unsigned fBase = smb + SM_FACT + buf * FACT_BUF;
#pragma unroll
    for (int ks = 0; ks < NKS; ks++) {
      const int half = (ks >= 4);
      const int kb = (ks - (half ? 4 : 0)) * 32 + xoff;
      const unsigned aB = smb + SM_ENT + half * ENT_HALF;
      const unsigned bB = fBase + half * FACT_HALF;
      uint32_t af[2][4];
#pragma unroll
      for (int mi = 0; mi < 2; mi++)
        ldmx4(af[mi], aB + aRowOff[mi] + ((unsigned)kb ^ aXor[mi]));
      uint32_t bf[2][4];
#pragma unroll
      for (int njp = 0; njp < 2; njp++)
        ldmx4(bf[njp], bB + bRowOff[njp] + ((unsigned)kb ^ bXor[njp]));
#pragma unroll
      for (int mi = 0; mi < 2; mi++)
#pragma unroll
        for (int njp = 0; njp < 2; njp++) {
          mma16816(acc[mi][2 * njp],     af[mi], bf[njp][0], bf[njp][2]);
          mma16816(acc[mi][2 * njp + 1], af[mi], bf[njp][1], bf[njp][3]);
        }
    }

    // packed bf16x2 epilogue: rm = min(rm, A + d)
    const uint32_t* As = (const uint32_t*)(sm + SM_A + buf * A_BUF);
#pragma unroll
    for (int nj = 0; nj < 4; nj++) {
      const int c0 = 32 * wf + 8 * nj + 2 * tl;
      uint4 A0 = *(const uint4*)(As + c0 * 4);       // col c0:  b0..7 (4 bf16x2)
      uint4 A1 = *(const uint4*)(As + c0 * 4 + 4);   // col c0+1
#pragma unroll
      for (int mi = 0; mi < 2; mi++) {
        const float* d = acc[mi][nj];
#pragma unroll
        for (int h = 0; h < 2; h++) {
          uint32_t d0 = bcvt2(d[h * 2]);
          uint32_t d1 = bcvt2(d[h * 2 + 1]);
          uint32_t* r = rmP[mi][h];
          r[0] = minbf2(r[0], minbf2(addbf2(A0.x, d0), addbf2(A1.x, d1)));
          r[1] = minbf2(r[1], minbf2(addbf2(A0.y, d0), addbf2(A1.y, d1)));
          r[2] = minbf2(r[2], minbf2(addbf2(A0.z, d0), addbf2(A1.z, d1)));
          r[3] = minbf2(r[3], minbf2(addbf2(A0.w, d0), addbf2(A1.w, d1)));
        }
      }
    }
  }

  // reduce across the 4 tl lanes sharing each row, then atomics
#pragma unroll
  for (int mi = 0; mi < 2; mi++)
#pragma unroll
    for (int h = 0; h < 2; h++)
#pragma unroll
      for (int j = 0; j < 4; j++) {
        uint32_t v = rmP[mi][h][j];
        v = minbf2(v, __shfl_xor_sync(0xffffffffu, v, 1));
        v = minbf2(v, __shfl_xor_sync(0xffffffffu, v, 2));
        rmP[mi][h][j] = v;
      }
  if (tl == 0) {
#pragma unroll
    for (int mi = 0; mi < 2; mi++)
#pragma unroll
      for (int h = 0; h < 2; h++) {
        int n = n0 + 32 * wn + 16 * mi + 8 * h + g;
        if (n < N) {
#pragma unroll
          for (int j = 0; j < 4; j++) {
            uint32_t v = rmP[mi][h][j];
            float lo = __uint_as_float((v & 0xFFFFu) << 16);
            float hi = __uint_as_float(v & 0xFFFF0000u);
            atomicMinF(&g_min[z][2 * j][n], lo);
            atomicMinF(&g_min[z][2 * j + 1][n], hi);
          }
        }
      }
  }

  // fused finalize: last CTA for this (z, n-tile) writes the outputs
  __shared__ int s_last;
  __threadfence();
  __syncthreads();
  if (tid == 0)
    s_last = atomicAdd(&g_cnt[z][blockIdx.x], 1);
  __syncthreads();
  if (s_last == FSPLIT - 1) {
    __threadfence();
    for (int o = tid; o < BB * NTILE; o += 256) {
      int b = o / NTILE, nl = o - (o / NTILE) * NTILE;
      int n = n0 + nl;
      if (n < N) {
        float d2 = fmaxf(g_min[z][b][n] + g_e2[n], 0.f);
        out[((size_t)z * BB + b) * N + n] = expf(-0.5f * d2);
      }
    }
  }
}

// ---------------------------------------------------------------------------
extern "C" void kernel_launch(void* const* d_in, const int* in_sizes, int n_in,
                              void* d_out, int out_size) {
  const float* rel = (const float*)d_in[0];
  const float* a1  = (const float*)d_in[1];
  const float* a2  = (const float*)d_in[2];
  const float* fr  = (const float*)d_in[3];
  const float* f1  = (const float*)d_in[4];
  const float* f2  = (const float*)d_in[5];
  const float* ent = (const float*)d_in[6];
  int F = in_sizes[3] / EE;
  int N = in_sizes[6] / EE;

  cudaFuncSetAttribute(k_main, cudaFuncAttributeMaxDynamicSharedMemorySize, SM_TOTAL);

  dim3 pgrid((FPAD * KROW) / 256, 6);     // heavy branch = sel 0, first
  k_prep<<<pgrid, 256>>>(rel, a1, a2, fr, f1, f2, ent, N, F);

  dim3 grid(FPAD / NTILE, FSPLIT, 2);     // 64 x 2 x 2 = 256 CTAs, ~2/SM
  k_main<<<grid, 256, SM_TOTAL>>>((float*)d_out, N);
}

// round 8
// speedup vs baseline: 1.1436x; 1.1436x over previous
#include <cuda_runtime.h>
#include <cuda_bf16.h>
#include <math_constants.h>
#include <cstdint>

#define BB 8
#define EE 100
#define FPAD 4096
#define NTILE 64          // n rows per CTA tile
#define FCH 128           // f cols per chunk
#define FSPLIT 2
#define KROW 128          // bf16 per logical row (2 halves of 64)
#define NKS 7             // 7 x k16 = 112 (zeros past 99 contribute 0)

// smem layout
#define ENT_HALF 8192                   // 64 rows x 128B
#define FACT_HALF 16384                 // 128 rows x 128B
#define ENT_BYTES (2*ENT_HALF)          // 16KB, contiguous per n-tile
#define FACT_BUF (2*FACT_HALF)          // 32KB, contiguous per f-chunk
#define SM_ENT 0
#define SM_FACT ENT_BYTES               // 2 buffers
#define SM_A (SM_FACT + 2*FACT_BUF)     // 2 buffers of [128 f][8 b] bf16
#define A_BUF 2048
#define SM_MBAR (SM_A + 2*A_BUF)        // two 8B mbarriers
#define SM_TOTAL (SM_MBAR + 16)         // 86032 B (x2 CTAs/SM)

// ---- device scratch ----
__device__ __nv_bfloat16 g_Ab[2][FPAD][BB];    // A transposed (bf16), +INF for f>=F
__device__ float g_e2[FPAD];
__device__ float g_min[2][BB][FPAD];
// PRE-SWIZZLED tiled layouts (written by k_prep, bulk-copied by k_main):
// g_eb: [tile(64 rows)][half][8KB swizzled]   (-2*ent)
// g_fb: [z][chunk(128 rows)][half][16KB swizzled]
__device__ __nv_bfloat16 g_eb[FPAD * KROW];
__device__ __nv_bfloat16 g_fb[2][FPAD * KROW];
__device__ int g_cnt[2][FPAD / NTILE];         // arrival counters per (z, n-tile)

// ---- helpers ----
__device__ __forceinline__ unsigned swz(unsigned b) { return b ^ ((b >> 3) & 0x70); }
__device__ __forceinline__ unsigned smem_u32(const void* p) {
  return (unsigned)__cvta_generic_to_shared(p);
}
__device__ __forceinline__ void mbar_init(unsigned a, unsigned cnt) {
  asm volatile("mbarrier.init.shared.b64 [%0], %1;" :: "r"(a), "r"(cnt) : "memory");
}
__device__ __forceinline__ void mbar_expect(unsigned a, unsigned tx) {
  asm volatile("mbarrier.arrive.expect_tx.shared.b64 _, [%0], %1;"
               :: "r"(a), "r"(tx) : "memory");
}
__device__ __forceinline__ void bulk_g2s(unsigned dst, const void* src,
                                         unsigned bytes, unsigned mbar) {
  asm volatile(
    "cp.async.bulk.shared::cluster.global.mbarrier::complete_tx::bytes "
    "[%0], [%1], %2, [%3];"
    :: "r"(dst), "l"(src), "r"(bytes), "r"(mbar) : "memory");
}
__device__ __forceinline__ void mwait(unsigned a, unsigned par) {
  asm volatile("{\n\t.reg .pred P;\n\t"
               "W%=:\n\tmbarrier.try_wait.parity.acquire.cta.shared::cta.b64 P, [%0], %1, 0x989680;\n\t"
               "@P bra.uni D%=;\n\tbra.uni W%=;\n\tD%=:\n\t}"
               :: "r"(a), "r"(par) : "memory");
}
__device__ __forceinline__ void ldmx4(uint32_t* r, unsigned addr) {
  asm volatile("ldmatrix.sync.aligned.m8n8.x4.shared.b16 {%0,%1,%2,%3}, [%4];"
               : "=r"(r[0]), "=r"(r[1]), "=r"(r[2]), "=r"(r[3]) : "r"(addr));
}
__device__ __forceinline__ void mma16816(float* c, const uint32_t* a,
                                         uint32_t b0, uint32_t b1) {
  asm volatile("mma.sync.aligned.m16n8k16.row.col.f32.bf16.bf16.f32 "
               "{%0,%1,%2,%3}, {%4,%5,%6,%7}, {%8,%9}, {%0,%1,%2,%3};"
               : "+f"(c[0]), "+f"(c[1]), "+f"(c[2]), "+f"(c[3])
               : "r"(a[0]), "r"(a[1]), "r"(a[2]), "r"(a[3]), "r"(b0), "r"(b1));
}
__device__ __forceinline__ uint32_t bcvt2(float x) {
  uint32_t r; asm("cvt.rn.bf16x2.f32 %0, %1, %1;" : "=r"(r) : "f"(x)); return r;
}
__device__ __forceinline__ uint32_t addbf2(uint32_t a, uint32_t b) {
  uint32_t r; asm("add.rn.bf16x2 %0, %1, %2;" : "=r"(r) : "r"(a), "r"(b)); return r;
}
__device__ __forceinline__ uint32_t minbf2(uint32_t a, uint32_t b) {
  uint32_t r; asm("min.bf16x2 %0, %1, %2;" : "=r"(r) : "r"(a), "r"(b)); return r;
}
__device__ __forceinline__ void atomicMinF(float* addr, float v) {
  if (v >= 0.0f) atomicMin((int*)addr, __float_as_int(v));
  else           atomicMax((unsigned int*)addr, __float_as_uint(v));
}

// ---- fused prep kernel: blockIdx.y selects task ----
__global__ void k_prep(const float* __restrict__ rel, const float* __restrict__ a1,
                       const float* __restrict__ a2, const float* __restrict__ fr,
                       const float* __restrict__ f1, const float* __restrict__ f2,
                       const float* __restrict__ ent, int N, int F) {
  const int sel = blockIdx.y;
  const int tid = threadIdx.x;

  if (sel == 0) {
    if (blockIdx.x >= (FPAD * BB) / 256) return;
    __shared__ __align__(16) float q[3][BB][EE];
    for (int i = tid; i < 3 * BB * EE; i += 256) {
      int t = i / (BB * EE), rem = i - t * (BB * EE);
      int b = rem / EE, e = rem - b * EE;
      const float* s = (t == 0) ? rel : (t == 1 ? a1 : a2);
      q[t][b][e] = s[b * EE + e];
    }
    __syncthreads();
    int idx = blockIdx.x * 256 + tid;
    int f = idx >> 3, b = idx & 7;
    if (f >= F) {
      g_Ab[0][f][b] = __float2bfloat16(CUDART_INF_F);
      g_Ab[1][f][b] = __float2bfloat16(CUDART_INF_F);
      return;
    }
    const float4* pr = (const float4*)(fr + (size_t)f * EE);
    const float4* p1 = (const float4*)(f1 + (size_t)f * EE);
    const float4* p2 = (const float4*)(f2 + (size_t)f * EE);
    float sr = 0.f, s1v = 0.f, s2v = 0.f, n1 = 0.f, n2 = 0.f;
#pragma unroll 5
    for (int e4 = 0; e4 < EE / 4; e4++) {
      float4 vr = pr[e4], v1 = p1[e4], v2 = p2[e4];
      n1 += v1.x * v1.x + v1.y * v1.y + v1.z * v1.z + v1.w * v1.w;
      n2 += v2.x * v2.x + v2.y * v2.y + v2.z * v2.z + v2.w * v2.w;
      float4 qr = *(const float4*)&q[0][b][e4 * 4];
      float4 q1 = *(const float4*)&q[1][b][e4 * 4];
      float4 q2 = *(const float4*)&q[2][b][e4 * 4];
      float t;
      t = qr.x - vr.x; sr += t * t;  t = qr.y - vr.y; sr += t * t;
      t = qr.z - vr.z; sr += t * t;  t = qr.w - vr.w; sr += t * t;
      t = q1.x - v1.x; s1v += t * t; t = q1.y - v1.y; s1v += t * t;
      t = q1.z - v1.z; s1v += t * t; t = q1.w - v1.w; s1v += t * t;
      t = q2.x - v2.x; s2v += t * t; t = q2.y - v2.y; s2v += t * t;
      t = q2.z - v2.z; s2v += t * t; t = q2.w - v2.w; s2v += t * t;
    }
    g_Ab[0][f][b] = __float2bfloat16(sr + s1v + n2);  // sp pairs with fa2
    g_Ab[1][f][b] = __float2bfloat16(sr + s2v + n1);  // po pairs with fa1
  } else if (sel == 1) {
    if (blockIdx.x >= FPAD / 256) return;
    int n = blockIdx.x * 256 + tid;
    if (n >= N) return;
    const float4* e4p = (const float4*)ent;
    float s = 0.f;
#pragma unroll
    for (int qq = 0; qq < EE / 4; qq++) {
      float4 v = e4p[n * (EE / 4) + qq];
      s += v.x * v.x + v.y * v.y + v.z * v.z + v.w * v.w;
    }
    g_e2[n] = s;
  } else if (sel <= 4) {
    int idx = blockIdx.x * 256 + tid;
    int r = idx >> 7, j = idx & 127;
    const float* src = (sel == 2) ? ent : (sel == 3 ? f2 : f1);
    int rows = (sel == 2) ? N : F;
    float scale = (sel == 2) ? -2.0f : 1.0f;
    float v = (r < rows && j < EE) ? scale * src[r * EE + j] : 0.f;
    __nv_bfloat16 bv = __float2bfloat16(v);
    int half = j >> 6;
    int bih = (2 * j) & 127;
    if (sel == 2) {
      // ent: tile of 64 rows -> [tile][half 8KB][swz]
      unsigned off = (unsigned)(r >> 6) * 16384u + half * 8192u +
                     swz((r & 63) * 128 + bih);
      *(__nv_bfloat16*)((char*)g_eb + off) = bv;
    } else {
      // fact: chunk of 128 rows -> [chunk][half 16KB][swz]
      unsigned off = (unsigned)(r >> 7) * 32768u + half * 16384u +
                     swz((r & 127) * 128 + bih);
      *(__nv_bfloat16*)((char*)g_fb[sel - 3] + off) = bv;
    }
  } else {
    int i = blockIdx.x * 256 + tid;
    if (i < 2 * BB * FPAD) ((float*)g_min)[i] = CUDART_INF_F;
    if (i < 2 * (FPAD / NTILE)) ((int*)g_cnt)[i] = 0;
  }
}

// ---- main HMMA kernel (bulk-copy staging, fused finalize) ----
__global__ __launch_bounds__(256, 2) void k_main(float* __restrict__ out, int N) {
  extern __shared__ char sm[];
  const int tid = threadIdx.x;
  const int wid = tid >> 5;
  const int lane = tid & 31;
  const unsigned smb = smem_u32(sm);
  const int z = blockIdx.z;
  const int n0 = blockIdx.x * NTILE;
  const int f0base = blockIdx.y * (FPAD / FSPLIT);
  const int NCH = (FPAD / FSPLIT) / FCH;   // 16
  const char* fbB = (const char*)g_fb[z];
  const char* ebB = (const char*)g_eb;
  const unsigned mb0 = smb + SM_MBAR;

  const int wn = wid & 1, wf = wid >> 1;   // warp grid 2(n) x 4(f)
  const int g = lane >> 2, tl = lane & 3;
  const int lrow = lane & 7, mm = lane >> 3;

  // ldmatrix per-lane bases
  const int xoff = 16 * (mm >> 1);
  unsigned aRowOff[2], aXor[2];
#pragma unroll
  for (int mi = 0; mi < 2; mi++) {
    int r = 32 * wn + 16 * mi + lrow + 8 * (mm & 1);
    aRowOff[mi] = r * 128;
    aXor[mi] = (r & 7) * 16;
  }
  unsigned bRowOff[2], bXor[2];
#pragma unroll
  for (int njp = 0; njp < 2; njp++) {
    int r = 32 * wf + 16 * njp + lrow + 8 * (mm & 1);
    bRowOff[njp] = r * 128;
    bXor[njp] = (r & 7) * 16;
  }

  auto fSrc = [&](int c) { return fbB + (size_t)(f0base + c * FCH) * 256; };
  auto aSrc = [&](int c) { return (const char*)&g_Ab[z][f0base + c * FCH][0]; };

  if (tid == 0) {
    mbar_init(mb0, 1);
    mbar_init(mb0 + 8, 1);
  }
  __syncthreads();
  if (tid == 0) {
    mbar_expect(mb0, ENT_BYTES + FACT_BUF + A_BUF);
    bulk_g2s(smb + SM_ENT, ebB + (size_t)n0 * 256, ENT_BYTES, mb0);
    bulk_g2s(smb + SM_FACT, fSrc(0), FACT_BUF, mb0);
    bulk_g2s(smb + SM_A, aSrc(0), A_BUF, mb0);
    mbar_expect(mb0 + 8, FACT_BUF + A_BUF);
    bulk_g2s(smb + SM_FACT + FACT_BUF, fSrc(1), FACT_BUF, mb0 + 8);
    bulk_g2s(smb + SM_A + A_BUF, aSrc(1), A_BUF, mb0 + 8);
  }

  uint32_t rmP[2][2][4];   // [mi][rowhalf][b-pair], bf16x2, init +INF|+INF
#pragma unroll
  for (int mi = 0; mi < 2; mi++)
#pragma unroll
    for (int h = 0; h < 2; h++)
#pragma unroll
      for (int j = 0; j < 4; j++) rmP[mi][h][j] = 0x7F807F80u;

  for (int c = 0; c < NCH; c++) {
    const int buf = c & 1;
    mwait(mb0 + 8 * buf, (c >> 1) & 1);

    float acc[2][4][4];
#pragma unroll
    for (int mi = 0; mi < 2; mi++)
#pragma unroll
      for (int nj = 0; nj < 4; nj++)
#pragma unroll
        for (int k = 0; k < 4; k++) acc[mi][nj][k] = 0.f;

    const unsigned fBase = smb + SM_FACT + buf * FACT_BUF;
#pragma unroll
    for (int ks = 0; ks < NKS; ks++) {
      const int half = (ks >= 4);
      const int kb = (ks - (half ? 4 : 0)) * 32 + xoff;
      const unsigned aB = smb + SM_ENT + half * ENT_HALF;
      const unsigned bB = fBase + half * FACT_HALF;
      uint32_t af[2][4];
#pragma unroll
      for (int mi = 0; mi < 2; mi++)
        ldmx4(af[mi], aB + aRowOff[mi] + ((unsigned)kb ^ aXor[mi]));
      uint32_t bf[2][4];
#pragma unroll
      for (int njp = 0; njp < 2; njp++)
        ldmx4(bf[njp], bB + bRowOff[njp] + ((unsigned)kb ^ bXor[njp]));
#pragma unroll
      for (int mi = 0; mi < 2; mi++)
#pragma unroll
        for (int njp = 0; njp < 2; njp++) {
          mma16816(acc[mi][2 * njp],     af[mi], bf[njp][0], bf[njp][2]);
          mma16816(acc[mi][2 * njp + 1], af[mi], bf[njp][1], bf[njp][3]);
        }
    }

    // packed bf16x2 epilogue: rm = min(rm, A + d)
    const uint32_t* As = (const uint32_t*)(sm + SM_A + buf * A_BUF);
#pragma unroll
    for (int nj = 0; nj < 4; nj++) {
      const int c0 = 32 * wf + 8 * nj + 2 * tl;
      uint4 A0 = *(const uint4*)(As + c0 * 4);       // col c0:  b0..7 (4 bf16x2)
      uint4 A1 = *(const uint4*)(As + c0 * 4 + 4);   // col c0+1
#pragma unroll
      for (int mi = 0; mi < 2; mi++) {
        const float* d = acc[mi][nj];
#pragma unroll
        for (int h = 0; h < 2; h++) {
          uint32_t d0 = bcvt2(d[h * 2]);
          uint32_t d1 = bcvt2(d[h * 2 + 1]);
          uint32_t* r = rmP[mi][h];
          r[0] = minbf2(r[0], minbf2(addbf2(A0.x, d0), addbf2(A1.x, d1)));
          r[1] = minbf2(r[1], minbf2(addbf2(A0.y, d0), addbf2(A1.y, d1)));
          r[2] = minbf2(r[2], minbf2(addbf2(A0.z, d0), addbf2(A1.z, d1)));
          r[3] = minbf2(r[3], minbf2(addbf2(A0.w, d0), addbf2(A1.w, d1)));
        }
      }
    }

    __syncthreads();   // everyone done reading buf before refill
    if (c + 2 < NCH && tid == 0) {
      unsigned mb = mb0 + 8 * buf;
      mbar_expect(mb, FACT_BUF + A_BUF);
      bulk_g2s(fBase, fSrc(c + 2), FACT_BUF, mb);
      bulk_g2s(smb + SM_A + buf * A_BUF, aSrc(c + 2), A_BUF, mb);
    }
  }

  // reduce across the 4 tl lanes sharing each row, then atomics
#pragma unroll
  for (int mi = 0; mi < 2; mi++)
#pragma unroll
    for (int h = 0; h < 2; h++)
#pragma unroll
      for (int j = 0; j < 4; j++) {
        uint32_t v = rmP[mi][h][j];
        v = minbf2(v, __shfl_xor_sync(0xffffffffu, v, 1));
        v = minbf2(v, __shfl_xor_sync(0xffffffffu, v, 2));
        rmP[mi][h][j] = v;
      }
  if (tl == 0) {
#pragma unroll
    for (int mi = 0; mi < 2; mi++)
#pragma unroll
      for (int h = 0; h < 2; h++) {
        int n = n0 + 32 * wn + 16 * mi + 8 * h + g;
        if (n < N) {
#pragma unroll
          for (int j = 0; j < 4; j++) {
            uint32_t v = rmP[mi][h][j];
            float lo = __uint_as_float((v & 0xFFFFu) << 16);
            float hi = __uint_as_float(v & 0xFFFF0000u);
            atomicMinF(&g_min[z][2 * j][n], lo);
            atomicMinF(&g_min[z][2 * j + 1][n], hi);
          }
        }
      }
  }

  // fused finalize: last CTA for this (z, n-tile) writes the outputs
  __shared__ int s_last;
  __threadfence();
  __syncthreads();
  if (tid == 0)
    s_last = atomicAdd(&g_cnt[z][blockIdx.x], 1);
  __syncthreads();
  if (s_last == FSPLIT - 1) {
    __threadfence();
    for (int o = tid; o < BB * NTILE; o += 256) {
      int b = o / NTILE, nl = o - (o / NTILE) * NTILE;
      int n = n0 + nl;
      if (n < N) {
        float d2 = fmaxf(g_min[z][b][n] + g_e2[n], 0.f);
        out[((size_t)z * BB + b) * N + n] = expf(-0.5f * d2);
      }
    }
  }
}

// ---------------------------------------------------------------------------
extern "C" void kernel_launch(void* const* d_in, const int* in_sizes, int n_in,
                              void* d_out, int out_size) {
  const float* rel = (const float*)d_in[0];
  const float* a1  = (const float*)d_in[1];
  const float* a2  = (const float*)d_in[2];
  const float* fr  = (const float*)d_in[3];
  const float* f1  = (const float*)d_in[4];
  const float* f2  = (const float*)d_in[5];
  const float* ent = (const float*)d_in[6];
  int F = in_sizes[3] / EE;
  int N = in_sizes[6] / EE;

  cudaFuncSetAttribute(k_main, cudaFuncAttributeMaxDynamicSharedMemorySize, SM_TOTAL);

  dim3 pgrid((FPAD * KROW) / 256, 6);     // heavy branch = sel 0, first
  k_prep<<<pgrid, 256>>>(rel, a1, a2, fr, f1, f2, ent, N, F);

  dim3 grid(FPAD / NTILE, FSPLIT, 2);     // 64 x 2 x 2 = 256 CTAs, ~2/SM
  k_main<<<grid, 256, SM_TOTAL>>>((float*)d_out, N);
}

// round 10
// speedup vs baseline: 1.1634x; 1.0173x over previous
#include <cuda_runtime.h>
#include <cuda_bf16.h>
#include <math_constants.h>
#include <cstdint>

#define BB 8
#define EE 100
#define FPAD 4096
#define NTILE 64          // n rows per CTA tile
#define FCH 128           // f cols per chunk
#define FSPLIT 2
#define KROW 128          // bf16 per logical row (2 halves of 64)
#define NKS 7             // 7 x k16 = 112 (zeros past 99 contribute 0)

// smem layout
#define ENT_HALF 8192                   // 64 rows x 128B
#define FACT_HALF 16384                 // 128 rows x 128B
#define ENT_BYTES (2*ENT_HALF)          // 16KB, contiguous per n-tile
#define FACT_BUF (2*FACT_HALF)          // 32KB, contiguous per f-chunk
#define SM_ENT 0
#define SM_FACT ENT_BYTES               // 2 buffers
#define SM_A (SM_FACT + 2*FACT_BUF)     // 2 buffers of [128 f][8 b] bf16
#define A_BUF 2048
#define SM_MBAR (SM_A + 2*A_BUF)        // full0, full1, empty0, empty1 (8B each)
#define SM_TOTAL (SM_MBAR + 32)         // 86048 B (x2 CTAs/SM)

// ---- device scratch ----
__device__ __nv_bfloat16 g_Ab[2][FPAD][BB];    // A transposed (bf16), +INF for f>=F
__device__ float g_e2[FPAD];
__device__ float g_min[2][BB][FPAD];
// PRE-SWIZZLED tiled layouts (written by k_prep, bulk-copied by k_main):
// g_eb: [tile(64 rows)][half][8KB swizzled]   (-2*ent)
// g_fb: [z][chunk(128 rows)][half][16KB swizzled]
__device__ __nv_bfloat16 g_eb[FPAD * KROW];
__device__ __nv_bfloat16 g_fb[2][FPAD * KROW];
__device__ int g_cnt[2][FPAD / NTILE];         // arrival counters per (z, n-tile)

// ---- helpers ----
__device__ __forceinline__ unsigned swz(unsigned b) { return b ^ ((b >> 3) & 0x70); }
__device__ __forceinline__ unsigned smem_u32(const void* p) {
  return (unsigned)__cvta_generic_to_shared(p);
}
__device__ __forceinline__ void mbar_init(unsigned a, unsigned cnt) {
  asm volatile("mbarrier.init.shared.b64 [%0], %1;" :: "r"(a), "r"(cnt) : "memory");
}
__device__ __forceinline__ void mbar_expect(unsigned a, unsigned tx) {
  asm volatile("mbarrier.arrive.expect_tx.shared.b64 _, [%0], %1;"
               :: "r"(a), "r"(tx) : "memory");
}
__device__ __forceinline__ void mbar_arrive(unsigned a) {
  asm volatile("mbarrier.arrive.release.cta.shared::cta.b64 _, [%0];"
               :: "r"(a) : "memory");
}
__device__ __forceinline__ void bulk_g2s(unsigned dst, const void* src,
                                         unsigned bytes, unsigned mbar) {
  asm volatile(
    "cp.async.bulk.shared::cluster.global.mbarrier::complete_tx::bytes "
    "[%0], [%1], %2, [%3];"
    :: "r"(dst), "l"(src), "r"(bytes), "r"(mbar) : "memory");
}
__device__ __forceinline__ void mwait(unsigned a, unsigned par) {
  asm volatile("{\n\t.reg .pred P;\n\t"
               "W%=:\n\tmbarrier.try_wait.parity.acquire.cta.shared::cta.b64 P, [%0], %1, 0x989680;\n\t"
               "@P bra.uni D%=;\n\tbra.uni W%=;\n\tD%=:\n\t}"
               :: "r"(a), "r"(par) : "memory");
}
__device__ __forceinline__ void ldmx4(uint32_t* r, unsigned addr) {
  asm volatile("ldmatrix.sync.aligned.m8n8.x4.shared.b16 {%0,%1,%2,%3}, [%4];"
               : "=r"(r[0]), "=r"(r[1]), "=r"(r[2]), "=r"(r[3]) : "r"(addr));
}
__device__ __forceinline__ void mma16816(float* c, const uint32_t* a,
                                         uint32_t b0, uint32_t b1) {
  asm volatile("mma.sync.aligned.m16n8k16.row.col.f32.bf16.bf16.f32 "
               "{%0,%1,%2,%3}, {%4,%5,%6,%7}, {%8,%9}, {%0,%1,%2,%3};"
               : "+f"(c[0]), "+f"(c[1]), "+f"(c[2]), "+f"(c[3])
               : "r"(a[0]), "r"(a[1]), "r"(a[2]), "r"(a[3]), "r"(b0), "r"(b1));
}
__device__ __forceinline__ uint32_t bcvt2(float x) {
  uint32_t r; asm("cvt.rn.bf16x2.f32 %0, %1, %1;" : "=r"(r) : "f"(x)); return r;
}
__device__ __forceinline__ uint32_t addbf2(uint32_t a, uint32_t b) {
  uint32_t r; asm("add.rn.bf16x2 %0, %1, %2;" : "=r"(r) : "r"(a), "r"(b)); return r;
}
__device__ __forceinline__ uint32_t minbf2(uint32_t a, uint32_t b) {
  uint32_t r; asm("min.bf16x2 %0, %1, %2;" : "=r"(r) : "r"(a), "r"(b)); return r;
}
__device__ __forceinline__ void atomicMinF(float* addr, float v) {
  if (v >= 0.0f) atomicMin((int*)addr, __float_as_int(v));
  else           atomicMax((unsigned int*)addr, __float_as_uint(v));
}

// ---- fused prep kernel: grid (256, 6); blockIdx.y selects task ----
__global__ void k_prep(const float* __restrict__ rel, const float* __restrict__ a1,
                       const float* __restrict__ a2, const float* __restrict__ fr,
                       const float* __restrict__ f1, const float* __restrict__ f2,
                       const float* __restrict__ ent, int N, int F) {
  const int sel = blockIdx.y;
  const int tid = threadIdx.x;

  if (sel == 0) {
    if (blockIdx.x >= (FPAD * BB) / 256) return;
    __shared__ __align__(16) float q[3][BB][EE];
    for (int i = tid; i < 3 * BB * EE; i += 256) {
      int t = i / (BB * EE), rem = i - t * (BB * EE);
      int b = rem / EE, e = rem - b * EE;
      const float* s = (t == 0) ? rel : (t == 1 ? a1 : a2);
      q[t][b][e] = s[b * EE + e];
    }
    __syncthreads();
    int idx = blockIdx.x * 256 + tid;
    int f = idx >> 3, b = idx & 7;
    if (f >= F) {
      g_Ab[0][f][b] = __float2bfloat16(CUDART_INF_F);
      g_Ab[1][f][b] = __float2bfloat16(CUDART_INF_F);
      return;
    }
    const float4* pr = (const float4*)(fr + (size_t)f * EE);
    const float4* p1 = (const float4*)(f1 + (size_t)f * EE);
    const float4* p2 = (const float4*)(f2 + (size_t)f * EE);
    float sr = 0.f, s1v = 0.f, s2v = 0.f, n1 = 0.f, n2 = 0.f;
#pragma unroll 5
    for (int e4 = 0; e4 < EE / 4; e4++) {
      float4 vr = pr[e4], v1 = p1[e4], v2 = p2[e4];
      n1 += v1.x * v1.x + v1.y * v1.y + v1.z * v1.z + v1.w * v1.w;
      n2 += v2.x * v2.x + v2.y * v2.y + v2.z * v2.z + v2.w * v2.w;
      float4 qr = *(const float4*)&q[0][b][e4 * 4];
      float4 q1 = *(const float4*)&q[1][b][e4 * 4];
      float4 q2 = *(const float4*)&q[2][b][e4 * 4];
      float t;
      t = qr.x - vr.x; sr += t * t;  t = qr.y - vr.y; sr += t * t;
      t = qr.z - vr.z; sr += t * t;  t = qr.w - vr.w; sr += t * t;
      t = q1.x - v1.x; s1v += t * t; t = q1.y - v1.y; s1v += t * t;
      t = q1.z - v1.z; s1v += t * t; t = q1.w - v1.w; s1v += t * t;
      t = q2.x - v2.x; s2v += t * t; t = q2.y - v2.y; s2v += t * t;
      t = q2.z - v2.z; s2v += t * t; t = q2.w - v2.w; s2v += t * t;
    }
    g_Ab[0][f][b] = __float2bfloat16(sr + s1v + n2);  // sp pairs with fa2
    g_Ab[1][f][b] = __float2bfloat16(sr + s2v + n1);  // po pairs with fa1
  } else if (sel == 1) {
    if (blockIdx.x >= FPAD / 256) return;
    int n = blockIdx.x * 256 + tid;
    if (n >= N) return;
    const float4* e4p = (const float4*)ent;
    float s = 0.f;
#pragma unroll
    for (int qq = 0; qq < EE / 4; qq++) {
      float4 v = e4p[n * (EE / 4) + qq];
      s += v.x * v.x + v.y * v.y + v.z * v.z + v.w * v.w;
    }
    g_e2[n] = s;
  } else if (sel <= 4) {
    // vectorized swizzled convert: one 16B granule (8 cols) per thread
    int gi = blockIdx.x * 256 + tid;      // 0..65535
    int r = gi >> 4, gg = gi & 15;
    const float* src = (sel == 2) ? ent : (sel == 3 ? f2 : f1);
    int rows = (sel == 2) ? N : F;
    float scale = (sel == 2) ? -2.0f : 1.0f;
    __nv_bfloat16 h[8];
#pragma unroll
    for (int k = 0; k < 8; k++) {
      int j = gg * 8 + k;
      float v = (r < rows && j < EE) ? scale * src[(size_t)r * EE + j] : 0.f;
      h[k] = __float2bfloat16(v);
    }
    int half = gg >> 3;
    unsigned bih = (gg & 7) * 16;
    unsigned off;
    char* dst;
    if (sel == 2) {
      off = (unsigned)(r >> 6) * 16384u + half * 8192u + swz((r & 63) * 128 + bih);
      dst = (char*)g_eb;
    } else {
      off = (unsigned)(r >> 7) * 32768u + half * 16384u + swz((r & 127) * 128 + bih);
      dst = (char*)g_fb[sel - 3];
    }
    *(uint4*)(dst + off) = *(uint4*)h;
  } else {
    // init: 2*BB*FPAD = 65536 floats -> exactly 256 blocks x 256 threads
    int i = blockIdx.x * 256 + tid;
    ((float*)g_min)[i] = CUDART_INF_F;
    if (i < 2 * (FPAD / NTILE)) ((int*)g_cnt)[i] = 0;
  }
}

// ---- main HMMA kernel (bulk staging, full/empty mbarrier pipeline) ----
__global__ __launch_bounds__(256, 2) void k_main(float* __restrict__ out, int N) {
  extern __shared__ char sm[];
  const int tid = threadIdx.x;
  const int wid = tid >> 5;
  const int lane = tid & 31;
  const unsigned smb = smem_u32(sm);
  const int z = blockIdx.z;
  const int n0 = blockIdx.x * NTILE;
  const int f0base = blockIdx.y * (FPAD / FSPLIT);
  const int NCH = (FPAD / FSPLIT) / FCH;   // 16
  const char* fbB = (const char*)g_fb[z];
  const char* ebB = (const char*)g_eb;
  const unsigned mbF = smb + SM_MBAR;       // full[0], full[1]
  const unsigned mbE = smb + SM_MBAR + 16;  // empty[0], empty[1]

  const int wn = wid & 1, wf = wid >> 1;   // warp grid 2(n) x 4(f)
  const int g = lane >> 2, tl = lane & 3;
  const int lrow = lane & 7, mm = lane >> 3;

  // ldmatrix per-lane bases
  const int xoff = 16 * (mm >> 1);
  unsigned aRowOff[2], aXor[2];
#pragma unroll
  for (int mi = 0; mi < 2; mi++) {
    int r = 32 * wn + 16 * mi + lrow + 8 * (mm & 1);
    aRowOff[mi] = r * 128;
    aXor[mi] = (r & 7) * 16;
  }
  unsigned bRowOff[2], bXor[2];
#pragma unroll
  for (int njp = 0; njp < 2; njp++) {
    int r = 32 * wf + 16 * njp + lrow + 8 * (mm & 1);
    bRowOff[njp] = r * 128;
    bXor[njp] = (r & 7) * 16;
  }

  auto fSrc = [&](int c) { return fbB + (size_t)(f0base + c * FCH) * 256; };
  auto aSrc = [&](int c) { return (const char*)&g_Ab[z][f0base + c * FCH][0]; };

  if (tid == 0) {
    mbar_init(mbF, 1);
    mbar_init(mbF + 8, 1);
    mbar_init(mbE, 256);
    mbar_init(mbE + 8, 256);
  }
  __syncthreads();
  if (tid == 0) {
    mbar_expect(mbF, ENT_BYTES + FACT_BUF + A_BUF);
    bulk_g2s(smb + SM_ENT, ebB + (size_t)n0 * 256, ENT_BYTES, mbF);
    bulk_g2s(smb + SM_FACT, fSrc(0), FACT_BUF, mbF);
    bulk_g2s(smb + SM_A, aSrc(0), A_BUF, mbF);
    mbar_expect(mbF + 8, FACT_BUF + A_BUF);
    bulk_g2s(smb + SM_FACT + FACT_BUF, fSrc(1), FACT_BUF, mbF + 8);
    bulk_g2s(smb + SM_A + A_BUF, aSrc(1), A_BUF, mbF + 8);
  }

  uint32_t rmP[2][2][4];   // [mi][rowhalf][b-pair], bf16x2, init +INF|+INF
#pragma unroll
  for (int mi = 0; mi < 2; mi++)
#pragma unroll
    for (int h = 0; h < 2; h++)
#pragma unroll
      for (int j = 0; j < 4; j++) rmP[mi][h][j] = 0x7F807F80u;

  for (int c = 0; c < NCH; c++) {
    const int buf = c & 1;
    const unsigned ph = (c >> 1) & 1;
    mwait(mbF + 8 * buf, ph);

    float acc[2][4][4];
#pragma unroll
    for (int mi = 0; mi < 2; mi++)
#pragma unroll
      for (int nj = 0; nj < 4; nj++)
#pragma unroll
        for (int k = 0; k < 4; k++) acc[mi][nj][k] = 0.f;

    const unsigned fBase = smb + SM_FACT + buf * FACT_BUF;
#pragma unroll
    for (int ks = 0; ks < NKS; ks++) {
      const int half = (ks >= 4);
      const int kb = (ks - (half ? 4 : 0)) * 32 + xoff;
      const unsigned aB = smb + SM_ENT + half * ENT_HALF;
      const unsigned bB = fBase + half * FACT_HALF;
      uint32_t af[2][4];
#pragma unroll
      for (int mi = 0; mi < 2; mi++)
        ldmx4(af[mi], aB + aRowOff[mi] + ((unsigned)kb ^ aXor[mi]));
      uint32_t bf[2][4];
#pragma unroll
      for (int njp = 0; njp < 2; njp++)
        ldmx4(bf[njp], bB + bRowOff[njp] + ((unsigned)kb ^ bXor[njp]));
#pragma unroll
      for (int mi = 0; mi < 2; mi++)
#pragma unroll
        for (int njp = 0; njp < 2; njp++) {
          mma16816(acc[mi][2 * njp],     af[mi], bf[njp][0], bf[njp][2]);
          mma16816(acc[mi][2 * njp + 1], af[mi], bf[njp][1], bf[njp][3]);
        }
    }

    // packed bf16x2 epilogue: rm = min(rm, A + d)
    const uint32_t* As = (const uint32_t*)(sm + SM_A + buf * A_BUF);
#pragma unroll
    for (int nj = 0; nj < 4; nj++) {
      const int c0 = 32 * wf + 8 * nj + 2 * tl;
      uint4 A0 = *(const uint4*)(As + c0 * 4);       // col c0:  b0..7 (4 bf16x2)
      uint4 A1 = *(const uint4*)(As + c0 * 4 + 4);   // col c0+1
#pragma unroll
      for (int mi = 0; mi < 2; mi++) {
        const float* d = acc[mi][nj];
#pragma unroll
        for (int h = 0; h < 2; h++) {
          uint32_t d0 = bcvt2(d[h * 2]);
          uint32_t d1 = bcvt2(d[h * 2 + 1]);
          uint32_t* r = rmP[mi][h];
          r[0] = minbf2(r[0], minbf2(addbf2(A0.x, d0), addbf2(A1.x, d1)));
          r[1] = minbf2(r[1], minbf2(addbf2(A0.y, d0), addbf2(A1.y, d1)));
          r[2] = minbf2(r[2], minbf2(addbf2(A0.z, d0), addbf2(A1.z, d1)));
          r[3] = minbf2(r[3], minbf2(addbf2(A0.w, d0), addbf2(A1.w, d1)));
        }
      }
    }

    // consumer release: this thread is done reading buf
    mbar_arrive(mbE + 8 * buf);
    // producer: refill buf for chunk c+2 once ALL threads released it
    if (c + 2 < NCH && tid == 0) {
      mwait(mbE + 8 * buf, ph);
      mbar_expect(mbF + 8 * buf, FACT_BUF + A_BUF);
      bulk_g2s(fBase, fSrc(c + 2), FACT_BUF, mbF + 8 * buf);
      bulk_g2s(smb + SM_A + buf * A_BUF, aSrc(c + 2), A_BUF, mbF + 8 * buf);
    }
  }

  // reduce across the 4 tl lanes sharing each row, then atomics
#pragma unroll
  for (int mi = 0; mi < 2; mi++)
#pragma unroll
    for (int h = 0; h < 2; h++)
#pragma unroll
      for (int j = 0; j < 4; j++) {
        uint32_t v = rmP[mi][h][j];
        v = minbf2(v, __shfl_xor_sync(0xffffffffu, v, 1));
        v = minbf2(v, __shfl_xor_sync(0xffffffffu, v, 2));
        rmP[mi][h][j] = v;
      }
  if (tl == 0) {
#pragma unroll
    for (int mi = 0; mi < 2; mi++)
#pragma unroll
      for (int h = 0; h < 2; h++) {
        int n = n0 + 32 * wn + 16 * mi + 8 * h + g;
        if (n < N) {
#pragma unroll
          for (int j = 0; j < 4; j++) {
            uint32_t v = rmP[mi][h][j];
            float lo = __uint_as_float((v & 0xFFFFu) << 16);
            float hi = __uint_as_float(v & 0xFFFF0000u);
            atomicMinF(&g_min[z][2 * j][n], lo);
            atomicMinF(&g_min[z][2 * j + 1][n], hi);
          }
        }
      }
  }

  // fused finalize: last CTA for this (z, n-tile) writes the outputs
  __shared__ int s_last;
  __threadfence();
  __syncthreads();
  if (tid == 0)
    s_last = atomicAdd(&g_cnt[z][blockIdx.x], 1);
  __syncthreads();
  if (s_last == FSPLIT - 1) {
    __threadfence();
    for (int o = tid; o < BB * NTILE; o += 256) {
      int b = o / NTILE, nl = o - (o / NTILE) * NTILE;
      int n = n0 + nl;
      if (n < N) {
        float d2 = fmaxf(g_min[z][b][n] + g_e2[n], 0.f);
        out[((size_t)z * BB + b) * N + n] = expf(-0.5f * d2);
      }
    }
  }
}

// ---------------------------------------------------------------------------
extern "C" void kernel_launch(void* const* d_in, const int* in_sizes, int n_in,
                              void* d_out, int out_size) {
  const float* rel = (const float*)d_in[0];
  const float* a1  = (const float*)d_in[1];
  const float* a2  = (const float*)d_in[2];
  const float* fr  = (const float*)d_in[3];
  const float* f1  = (const float*)d_in[4];
  const float* f2  = (const float*)d_in[5];
  const float* ent = (const float*)d_in[6];
  int F = in_sizes[3] / EE;
  int N = in_sizes[6] / EE;

  cudaFuncSetAttribute(k_main, cudaFuncAttributeMaxDynamicSharedMemorySize, SM_TOTAL);

  dim3 pgrid(256, 6);
  k_prep<<<pgrid, 256>>>(rel, a1, a2, fr, f1, f2, ent, N, F);

  dim3 grid(FPAD / NTILE, FSPLIT, 2);     // 64 x 2 x 2 = 256 CTAs, ~2/SM
  k_main<<<grid, 256, SM_TOTAL>>>((float*)d_out, N);
}